// round 7
// baseline (speedup 1.0000x reference)
#include <cuda_runtime.h>
#include <cstdint>

// Problem constants
#define OUT_N 11008
#define IN_K  4096
#define GS    128
#define NG    32          // groups per row
#define M_TOK 8

// Tiling
#define BLOCK            256
#define WARPS            8
#define T_ROWS           2                      // output rows per warp
#define ROWS_PER_BLOCK   (WARPS * T_ROWS)       // 16 -> grid 688

typedef unsigned long long u64;

// ---- packed f32x2 helpers (Blackwell FFMA2 path; ptxas won't emit from C++) ----
__device__ __forceinline__ u64 pkf(float lo, float hi) {
    u64 r; asm("mov.b64 %0, {%1, %2};" : "=l"(r) : "f"(lo), "f"(hi)); return r;
}
__device__ __forceinline__ u64 pki(unsigned lo, unsigned hi) {
    u64 r; asm("mov.b64 %0, {%1, %2};" : "=l"(r) : "r"(lo), "r"(hi)); return r;
}
__device__ __forceinline__ u64 add2(u64 a, u64 b) {
    u64 r; asm("add.rn.f32x2 %0, %1, %2;" : "=l"(r) : "l"(a), "l"(b)); return r;
}
__device__ __forceinline__ u64 mul2(u64 a, u64 b) {
    u64 r; asm("mul.rn.f32x2 %0, %1, %2;" : "=l"(r) : "l"(a), "l"(b)); return r;
}
__device__ __forceinline__ u64 fma2(u64 a, u64 b, u64 c) {
    u64 r; asm("fma.rn.f32x2 %0, %1, %2, %3;" : "=l"(r) : "l"(a), "l"(b), "l"(c)); return r;
}
__device__ __forceinline__ float2 upk(u64 a) {
    float lo, hi; asm("mov.b64 {%0, %1}, %2;" : "=f"(lo), "=f"(hi) : "l"(a));
    return make_float2(lo, hi);
}

// Barrier-free, smem-free: x (128 KB) and sc/qz stay L1-resident per SM;
// weights stream through with .cs (evict-first). Target: 3 CTAs/SM = 24 warps.
__global__ void __launch_bounds__(BLOCK, 3)
qlinear_pergrp_kernel(const float* __restrict__ x,
                      const int*   __restrict__ qw,
                      const int*   __restrict__ qz,
                      const float* __restrict__ sc,
                      float*       __restrict__ out)
{
    const int tid  = threadIdx.x;
    const int warp = tid >> 5;
    const int lane = tid & 31;

    const int row0 = blockIdx.x * ROWS_PER_BLOCK + warp * T_ROWS;

    // weight row bases for the warp's two output rows
    const int4* q0 = (const int4*)(qw + (size_t)row0 * IN_K) + lane;
    const int4* q1 = q0 + (IN_K / 4);

    const float* scp = sc + (size_t)row0 * NG;  // [2][NG] for this warp
    const int*   qzp = qz + (size_t)row0 * NG;

    u64 acc[T_ROWS][M_TOK];
#pragma unroll
    for (int r = 0; r < T_ROWS; r++)
#pragma unroll
        for (int m = 0; m < M_TOK; m++) acc[r][m] = 0ULL;

    // software pipeline: group g's weights loaded in iteration g-1
    int4 w0 = __ldcs(q0);
    int4 w1 = __ldcs(q1);

    for (int g = 0; g < NG; g++) {
        // issue next group's loads first (one group lookahead in flight)
        int4 n0, n1;
        if (g + 1 < NG) {
            n0 = __ldcs(q0 + (g + 1) * 32);
            n1 = __ldcs(q1 + (g + 1) * 32);
        }

        // per-group constants: warp-uniform L1-hit loads
        const float s0 = __ldg(scp + g);
        const float s1 = __ldg(scp + NG + g);
        const int   z0 = __ldg(qzp + g);
        const int   z1 = __ldg(qzp + NG + g);
        // -(2^23 + z) exactly: set magic exponent then flip sign bit
        const float nz0 = __int_as_float((z0 | 0x4B000000) ^ 0x80000000);
        const float nz1 = __int_as_float((z1 | 0x4B000000) ^ 0x80000000);
        const u64 ss0 = pkf(s0, s0),  zz0 = pkf(nz0, nz0);
        const u64 ss1 = pkf(s1, s1),  zz1 = pkf(nz1, nz1);

        // dequant both rows, k-packed f32x2:
        // as_float(q|0x4B000000) == 2^23+q ; (2^23+q) + (-(2^23+z)) is Sterbenz-exact
        const u64 a01 = mul2(add2(pki((unsigned)w0.x | 0x4B000000u,
                                      (unsigned)w0.y | 0x4B000000u), zz0), ss0);
        const u64 a23 = mul2(add2(pki((unsigned)w0.z | 0x4B000000u,
                                      (unsigned)w0.w | 0x4B000000u), zz0), ss0);
        const u64 b01 = mul2(add2(pki((unsigned)w1.x | 0x4B000000u,
                                      (unsigned)w1.y | 0x4B000000u), zz1), ss1);
        const u64 b23 = mul2(add2(pki((unsigned)w1.z | 0x4B000000u,
                                      (unsigned)w1.w | 0x4B000000u), zz1), ss1);

        // x: L1-resident LDG.128 per token (constant m*IN_K offsets off one base)
        const float4* xb = (const float4*)x + g * (GS / 4) + lane;
#pragma unroll
        for (int m = 0; m < M_TOK; m++) {
            const float4 xv = __ldg(xb + m * (IN_K / 4));
            const u64 x01 = pkf(xv.x, xv.y);    // adjacent regs -> free pair
            const u64 x23 = pkf(xv.z, xv.w);
            acc[0][m] = fma2(a01, x01, acc[0][m]);
            acc[0][m] = fma2(a23, x23, acc[0][m]);
            acc[1][m] = fma2(b01, x01, acc[1][m]);
            acc[1][m] = fma2(b23, x23, acc[1][m]);
        }

        w0 = n0;
        w1 = n1;
    }

    // ---- fold f32x2 halves, then intra-warp reduction over the k-split ----
#pragma unroll
    for (int r = 0; r < T_ROWS; r++)
#pragma unroll
        for (int m = 0; m < M_TOK; m++) {
            const float2 v = upk(acc[r][m]);
            float s = v.x + v.y;
#pragma unroll
            for (int off = 16; off > 0; off >>= 1)
                s += __shfl_xor_sync(0xffffffffu, s, off);
            if (lane == 0)
                out[m * OUT_N + (row0 + r)] = s;
        }
}

extern "C" void kernel_launch(void* const* d_in, const int* in_sizes, int n_in,
                              void* d_out, int out_size)
{
    const float* x  = (const float*)d_in[0];   // [8, 4096] f32
    const int*   qw = (const int*)  d_in[1];   // [11008, 4096] int32 in [0,15]
    const int*   qz = (const int*)  d_in[2];   // [11008, 32] int32
    const float* sc = (const float*)d_in[3];   // [11008, 32] f32
    float* out = (float*)d_out;                // [8, 11008] f32

    const int grid = OUT_N / ROWS_PER_BLOCK;   // 688
    qlinear_pergrp_kernel<<<grid, BLOCK>>>(x, qw, qz, sc, out);
}

// round 8
// speedup vs baseline: 1.5392x; 1.5392x over previous
#include <cuda_runtime.h>
#include <cstdint>

// Problem constants
#define OUT_N 11008
#define IN_K  4096
#define GS    128
#define NG    32          // groups per row
#define M_TOK 8

// Tiling
#define BLOCK            256
#define WARPS            8
#define T_ROWS           2                      // output rows per warp
#define ROWS_PER_BLOCK   (WARPS * T_ROWS)       // 16 -> grid 688
#define CHUNK            1024                   // k-columns of x staged in smem
#define GPC              (CHUNK / GS)           // 8 groups per chunk
#define NCHUNK           (IN_K / CHUNK)         // 4

typedef unsigned long long u64;

// ---- packed f32x2 helpers (Blackwell FFMA2 path; ptxas won't emit from C++) ----
__device__ __forceinline__ u64 pkf(float lo, float hi) {
    u64 r; asm("mov.b64 %0, {%1, %2};" : "=l"(r) : "f"(lo), "f"(hi)); return r;
}
__device__ __forceinline__ u64 pki(unsigned lo, unsigned hi) {
    u64 r; asm("mov.b64 %0, {%1, %2};" : "=l"(r) : "r"(lo), "r"(hi)); return r;
}
__device__ __forceinline__ u64 add2(u64 a, u64 b) {
    u64 r; asm("add.rn.f32x2 %0, %1, %2;" : "=l"(r) : "l"(a), "l"(b)); return r;
}
__device__ __forceinline__ u64 mul2(u64 a, u64 b) {
    u64 r; asm("mul.rn.f32x2 %0, %1, %2;" : "=l"(r) : "l"(a), "l"(b)); return r;
}
__device__ __forceinline__ u64 fma2(u64 a, u64 b, u64 c) {
    u64 r; asm("fma.rn.f32x2 %0, %1, %2, %3;" : "=l"(r) : "l"(a), "l"(b), "l"(c)); return r;
}
__device__ __forceinline__ float2 upk(u64 a) {
    float lo, hi; asm("mov.b64 {%0, %1}, %2;" : "=f"(lo), "=f"(hi) : "l"(a));
    return make_float2(lo, hi);
}

// x staged in smem (LDS path keeps weight LDGs' L1tex queue shallow);
// per-group consts via warp-uniform __ldg; 84-reg cap -> 3 CTAs/SM = 24 warps.
__global__ void __launch_bounds__(BLOCK, 3)
qlinear_pergrp_kernel(const float* __restrict__ x,
                      const int*   __restrict__ qw,
                      const int*   __restrict__ qz,
                      const float* __restrict__ sc,
                      float*       __restrict__ out)
{
    __shared__ float4 xs4[M_TOK][CHUNK / 4];          // 32 KB

    const int tid  = threadIdx.x;
    const int warp = tid >> 5;
    const int lane = tid & 31;

    const int row0 = blockIdx.x * ROWS_PER_BLOCK + warp * T_ROWS;

    const int4* q0 = (const int4*)(qw + (size_t)row0 * IN_K) + lane;
    const int4* q1 = q0 + (IN_K / 4);

    const float* scp = sc + (size_t)row0 * NG;  // [2][NG] for this warp
    const int*   qzp = qz + (size_t)row0 * NG;

    u64 acc[T_ROWS][M_TOK];
#pragma unroll
    for (int r = 0; r < T_ROWS; r++)
#pragma unroll
        for (int m = 0; m < M_TOK; m++) acc[r][m] = 0ULL;

    // software pipeline: group g's weights loaded one body ahead
    int4 w0 = __ldcs(q0);
    int4 w1 = __ldcs(q1);

    const float4* xg = (const float4*)x;

    for (int c = 0; c < NCHUNK; c++) {
        __syncthreads();
        // cooperative x chunk load: 2048 float4, fully coalesced (x L2-resident)
#pragma unroll
        for (int it = 0; it < (M_TOK * (CHUNK / 4)) / BLOCK; it++) {
            const int idx = it * BLOCK + tid;
            const int m  = idx >> 8;          // / 256
            const int i4 = idx & 255;
            xs4[m][i4] = xg[m * (IN_K / 4) + c * (CHUNK / 4) + i4];
        }
        __syncthreads();

#pragma unroll
        for (int jj = 0; jj < GPC; jj++) {
            const int g = c * GPC + jj;

            // issue next group's weight loads first (stay one body ahead;
            // prefetch legally crosses the next chunk barrier — registers only)
            int4 n0, n1;
            if (g + 1 < NG) {
                n0 = __ldcs(q0 + (g + 1) * 32);
                n1 = __ldcs(q1 + (g + 1) * 32);
            }

            // per-group constants: warp-uniform L1-hit loads
            const float s0 = __ldg(scp + g);
            const float s1 = __ldg(scp + NG + g);
            const int   z0 = __ldg(qzp + g);
            const int   z1 = __ldg(qzp + NG + g);
            // -(2^23 + z) exactly: set magic exponent then flip sign bit
            const float nz0 = __int_as_float((z0 | 0x4B000000) ^ 0x80000000);
            const float nz1 = __int_as_float((z1 | 0x4B000000) ^ 0x80000000);
            const u64 ss0 = pkf(s0, s0),  zz0 = pkf(nz0, nz0);
            const u64 ss1 = pkf(s1, s1),  zz1 = pkf(nz1, nz1);

            // dequant both rows, k-packed f32x2:
            // as_float(q|0x4B000000) == 2^23+q ; (2^23+q) + (-(2^23+z)) Sterbenz-exact
            const u64 a01 = mul2(add2(pki((unsigned)w0.x | 0x4B000000u,
                                          (unsigned)w0.y | 0x4B000000u), zz0), ss0);
            const u64 a23 = mul2(add2(pki((unsigned)w0.z | 0x4B000000u,
                                          (unsigned)w0.w | 0x4B000000u), zz0), ss0);
            const u64 b01 = mul2(add2(pki((unsigned)w1.x | 0x4B000000u,
                                          (unsigned)w1.y | 0x4B000000u), zz1), ss1);
            const u64 b23 = mul2(add2(pki((unsigned)w1.z | 0x4B000000u,
                                          (unsigned)w1.w | 0x4B000000u), zz1), ss1);

            // stream x per token (LDS.128, conflict-free) to keep liveness low
#pragma unroll
            for (int m = 0; m < M_TOK; m++) {
                const float4 xv = xs4[m][jj * 32 + lane];
                const u64 x01 = pkf(xv.x, xv.y);    // adjacent regs -> free pair
                const u64 x23 = pkf(xv.z, xv.w);
                acc[0][m] = fma2(a01, x01, acc[0][m]);
                acc[0][m] = fma2(a23, x23, acc[0][m]);
                acc[1][m] = fma2(b01, x01, acc[1][m]);
                acc[1][m] = fma2(b23, x23, acc[1][m]);
            }

            w0 = n0;
            w1 = n1;
        }
    }

    // ---- fold f32x2 halves, then intra-warp reduction over the k-split ----
#pragma unroll
    for (int r = 0; r < T_ROWS; r++)
#pragma unroll
        for (int m = 0; m < M_TOK; m++) {
            const float2 v = upk(acc[r][m]);
            float s = v.x + v.y;
#pragma unroll
            for (int off = 16; off > 0; off >>= 1)
                s += __shfl_xor_sync(0xffffffffu, s, off);
            if (lane == 0)
                out[m * OUT_N + (row0 + r)] = s;
        }
}

extern "C" void kernel_launch(void* const* d_in, const int* in_sizes, int n_in,
                              void* d_out, int out_size)
{
    const float* x  = (const float*)d_in[0];   // [8, 4096] f32
    const int*   qw = (const int*)  d_in[1];   // [11008, 4096] int32 in [0,15]
    const int*   qz = (const int*)  d_in[2];   // [11008, 32] int32
    const float* sc = (const float*)d_in[3];   // [11008, 32] f32
    float* out = (float*)d_out;                // [8, 11008] f32

    const int grid = OUT_N / ROWS_PER_BLOCK;   // 688
    qlinear_pergrp_kernel<<<grid, BLOCK>>>(x, qw, qz, sc, out);
}

// round 10
// speedup vs baseline: 1.9459x; 1.2642x over previous
#include <cuda_runtime.h>
#include <cstdint>

// Problem constants
#define OUT_N 11008
#define IN_K  4096
#define GS    128
#define NG    32          // groups per row
#define M_TOK 8

// Tiling
#define BLOCK            256
#define WARPS            8
#define T_ROWS           2                      // output rows per warp
#define ROWS_PER_BLOCK   (WARPS * T_ROWS)       // 16 -> grid 688
#define SLOTS            5                      // smem stage slots
#define DEPTH            4                      // cp.async groups in flight

typedef unsigned long long u64;

// ---- packed f32x2 helpers (Blackwell FFMA2 path; ptxas won't emit from C++) ----
__device__ __forceinline__ u64 pkf(float lo, float hi) {
    u64 r; asm("mov.b64 %0, {%1, %2};" : "=l"(r) : "f"(lo), "f"(hi)); return r;
}
__device__ __forceinline__ u64 pki(unsigned lo, unsigned hi) {
    u64 r; asm("mov.b64 %0, {%1, %2};" : "=l"(r) : "r"(lo), "r"(hi)); return r;
}
__device__ __forceinline__ u64 add2(u64 a, u64 b) {
    u64 r; asm("add.rn.f32x2 %0, %1, %2;" : "=l"(r) : "l"(a), "l"(b)); return r;
}
__device__ __forceinline__ u64 mul2(u64 a, u64 b) {
    u64 r; asm("mul.rn.f32x2 %0, %1, %2;" : "=l"(r) : "l"(a), "l"(b)); return r;
}
__device__ __forceinline__ u64 fma2(u64 a, u64 b, u64 c) {
    u64 r; asm("fma.rn.f32x2 %0, %1, %2, %3;" : "=l"(r) : "l"(a), "l"(b), "l"(c)); return r;
}
__device__ __forceinline__ float2 upk(u64 a) {
    float lo, hi; asm("mov.b64 {%0, %1}, %2;" : "=f"(lo), "=f"(hi) : "l"(a));
    return make_float2(lo, hi);
}

// ---- cp.async (LDGSTS) helpers ----
__device__ __forceinline__ void cpa16(void* smem_ptr, const void* gptr) {
    const unsigned sa = (unsigned)__cvta_generic_to_shared(smem_ptr);
    asm volatile("cp.async.cg.shared.global [%0], [%1], 16;" :: "r"(sa), "l"(gptr));
}
__device__ __forceinline__ void cpa_commit() {
    asm volatile("cp.async.commit_group;");
}
__device__ __forceinline__ void cpa_wait_prior_depth_minus1() {
    asm volatile("cp.async.wait_group %0;" :: "n"(DEPTH - 1));
}

// One pipeline stage: weights for all 16 CTA rows of one group + x for that group.
struct Stage {
    int4   w[ROWS_PER_BLOCK][32];   // 8 KB : [row][lane]
    float4 xv[M_TOK][32];           // 4 KB : [token][lane]
};

// cp.async multistage pipeline: in-flight window = 4 stages * 12 KB per CTA,
// fully decoupled from the consumer's scoreboard. One barrier per group.
__global__ void __launch_bounds__(BLOCK, 3)
qlinear_pergrp_kernel(const float* __restrict__ x,
                      const int*   __restrict__ qw,
                      const int*   __restrict__ qz,
                      const float* __restrict__ sc,
                      float*       __restrict__ out)
{
    __shared__ Stage st[SLOTS];                 // 60 KB

    const int tid  = threadIdx.x;
    const int warp = tid >> 5;
    const int lane = tid & 31;
    const int row_blk = blockIdx.x * ROWS_PER_BLOCK;
    const int row0 = row_blk + warp * T_ROWS;

    // fill assignment: 768 16B chunks per stage, 3 per thread
    const int c0 = tid, c1 = tid + 256, c2 = tid + 512;

    const float* scp = sc + (size_t)row0 * NG;
    const int*   qzp = qz + (size_t)row0 * NG;

    // ---- fill helper ----
    auto fill = [&](int g, int slot) {
        // chunks 0..511: weights  (r = c>>5, i = c&31)
        // chunks 512..767: x      (m = (c-512)>>5, i = c&31)
        {   // c0 < 512 always (tid < 256)
            const int r = c0 >> 5, i = c0 & 31;
            cpa16(&st[slot].w[r][i],
                  qw + (size_t)(row_blk + r) * IN_K + g * GS + i * 4);
        }
        {   // c1 in [256, 512): weights
            const int r = c1 >> 5, i = c1 & 31;
            cpa16(&st[slot].w[r][i],
                  qw + (size_t)(row_blk + r) * IN_K + g * GS + i * 4);
        }
        {   // c2 in [512, 768): x
            const int m = (c2 - 512) >> 5, i = c2 & 31;
            cpa16(&st[slot].xv[m][i],
                  x + (size_t)m * IN_K + g * GS + i * 4);
        }
    };

    // ---- prologue: stages 0..DEPTH-1 in flight ----
#pragma unroll
    for (int s = 0; s < DEPTH; s++) {
        fill(s, s);
        cpa_commit();
    }

    u64 acc[T_ROWS][M_TOK];
#pragma unroll
    for (int r = 0; r < T_ROWS; r++)
#pragma unroll
        for (int m = 0; m < M_TOK; m++) acc[r][m] = 0ULL;

    int slot = 0, wslot = DEPTH;                // next read slot / next write slot

    for (int g = 0; g < NG; g++) {
        cpa_wait_prior_depth_minus1();          // own chunks of group g landed
        __syncthreads();                        // everyone's chunks visible

        // per-group constants: warp-uniform L1-hit loads
        const float s0 = __ldg(scp + g);
        const float s1 = __ldg(scp + NG + g);
        const int   z0 = __ldg(qzp + g);
        const int   z1 = __ldg(qzp + NG + g);
        const float nz0 = __int_as_float((z0 | 0x4B000000) ^ 0x80000000);
        const float nz1 = __int_as_float((z1 | 0x4B000000) ^ 0x80000000);
        const u64 ss0 = pkf(s0, s0),  zz0 = pkf(nz0, nz0);
        const u64 ss1 = pkf(s1, s1),  zz1 = pkf(nz1, nz1);

        // weights from smem: [row][lane] -> 512B contiguous per warp, conflict-free
        const int4 w0 = st[slot].w[warp * T_ROWS + 0][lane];
        const int4 w1 = st[slot].w[warp * T_ROWS + 1][lane];

        // dequant, k-packed f32x2:
        // as_float(q|0x4B000000) == 2^23+q ; (2^23+q) + (-(2^23+z)) is Sterbenz-exact
        const u64 a01 = mul2(add2(pki((unsigned)w0.x | 0x4B000000u,
                                      (unsigned)w0.y | 0x4B000000u), zz0), ss0);
        const u64 a23 = mul2(add2(pki((unsigned)w0.z | 0x4B000000u,
                                      (unsigned)w0.w | 0x4B000000u), zz0), ss0);
        const u64 b01 = mul2(add2(pki((unsigned)w1.x | 0x4B000000u,
                                      (unsigned)w1.y | 0x4B000000u), zz1), ss1);
        const u64 b23 = mul2(add2(pki((unsigned)w1.z | 0x4B000000u,
                                      (unsigned)w1.w | 0x4B000000u), zz1), ss1);

#pragma unroll
        for (int m = 0; m < M_TOK; m++) {
            const float4 xv = st[slot].xv[m][lane];   // LDS.128, conflict-free
            const u64 x01 = pkf(xv.x, xv.y);
            const u64 x23 = pkf(xv.z, xv.w);
            acc[0][m] = fma2(a01, x01, acc[0][m]);
            acc[0][m] = fma2(a23, x23, acc[0][m]);
            acc[1][m] = fma2(b01, x01, acc[1][m]);
            acc[1][m] = fma2(b23, x23, acc[1][m]);
        }

        // refill: writes wslot, never a slot any warp can still be reading
        // (5 slots + per-iteration barrier bound the skew)
        if (g + DEPTH < NG)
            fill(g + DEPTH, wslot);
        cpa_commit();                           // commit (possibly empty) keeps counts aligned

        if (++slot  == SLOTS) slot  = 0;
        if (++wslot == SLOTS) wslot = 0;
    }

    // ---- fold f32x2 halves, then intra-warp reduction over the k-split ----
#pragma unroll
    for (int r = 0; r < T_ROWS; r++)
#pragma unroll
        for (int m = 0; m < M_TOK; m++) {
            const float2 v = upk(acc[r][m]);
            float s = v.x + v.y;
#pragma unroll
            for (int off = 16; off > 0; off >>= 1)
                s += __shfl_xor_sync(0xffffffffu, s, off);
            if (lane == 0)
                out[m * OUT_N + (row0 + r)] = s;
        }
}

extern "C" void kernel_launch(void* const* d_in, const int* in_sizes, int n_in,
                              void* d_out, int out_size)
{
    const float* x  = (const float*)d_in[0];   // [8, 4096] f32
    const int*   qw = (const int*)  d_in[1];   // [11008, 4096] int32 in [0,15]
    const int*   qz = (const int*)  d_in[2];   // [11008, 32] int32
    const float* sc = (const float*)d_in[3];   // [11008, 32] f32
    float* out = (float*)d_out;                // [8, 11008] f32

    const int grid = OUT_N / ROWS_PER_BLOCK;   // 688
    qlinear_pergrp_kernel<<<grid, BLOCK>>>(x, qw, qz, sc, out);
}